// round 3
// baseline (speedup 1.0000x reference)
#include <cuda_runtime.h>

// Problem constants (fixed shapes)
#define BS    16
#define DIM   4096
#define NH    32
#define DH    128
#define SEQ   4096
#define NCOL  4096   // NH*DH
#define KS    64     // K-split for the 16xN GEMMs
#define NT    8      // attention k-tiles per (b,h)
#define TSZ   (SEQ / NT)   // 512 keys per tile

#define WEIGHT_ELEMS (BS * NH * SEQ)   // 2097152
#define BN (BS * NCOL)                 // 65536

// Scratch (device globals; no allocation allowed)
__device__ float g_qkv[3 * BN];             // q,k,v : [mat][b][h*128+d]
__device__ float g_part[3 * KS * BN];       // qkv GEMM k-split partials
__device__ float g_ctx[BN];                 // attention context [b][h*128+d]
__device__ float g_cpart[KS * BN];          // out-proj k-split partials
__device__ float g_am[BS * NH * NT];        // per-tile local max
__device__ float g_as[BS * NH * NT];        // per-tile local expsum
__device__ float g_actx[BS * NH * NT * DH]; // per-tile partial ctx

// ---------------------------------------------------------------------------
// 16xK @ KxN GEMM body: 128 threads, each thread owns 4 consecutive output
// columns (float4 W loads) for all 16 batch rows. Block covers 512 columns
// and DIM/KS = 64 K-rows. X staged in smem (broadcast reads).
// ---------------------------------------------------------------------------
__device__ __forceinline__ void gemm16_body(const float* __restrict__ X,
                                            const float* __restrict__ W,
                                            float* __restrict__ part)
{
    __shared__ __align__(16) float xs[32][16];
    const int j4 = blockIdx.x * 512 + threadIdx.x * 4;   // first of 4 columns
    const int d0 = blockIdx.y * (DIM / KS);              // 64 rows per split

    float4 acc[16];
#pragma unroll
    for (int b = 0; b < 16; b++) acc[b] = make_float4(0.f, 0.f, 0.f, 0.f);

    const float4* W4 = (const float4*)W;

    for (int dt = 0; dt < DIM / KS; dt += 32) {
        const int base = d0 + dt;
#pragma unroll
        for (int i = threadIdx.x; i < 512; i += 128) {
            int b = i >> 5, dd = i & 31;
            xs[dd][b] = X[b * DIM + base + dd];
        }
        __syncthreads();
#pragma unroll 8
        for (int dd = 0; dd < 32; dd++) {
            float4 w = W4[(size_t)(base + dd) * (NCOL / 4) + (j4 >> 2)];
            const float4* xv = (const float4*)xs[dd];
#pragma unroll
            for (int b4 = 0; b4 < 4; b4++) {
                float4 xb = xv[b4];
                acc[b4 * 4 + 0].x += xb.x * w.x; acc[b4 * 4 + 0].y += xb.x * w.y;
                acc[b4 * 4 + 0].z += xb.x * w.z; acc[b4 * 4 + 0].w += xb.x * w.w;
                acc[b4 * 4 + 1].x += xb.y * w.x; acc[b4 * 4 + 1].y += xb.y * w.y;
                acc[b4 * 4 + 1].z += xb.y * w.z; acc[b4 * 4 + 1].w += xb.y * w.w;
                acc[b4 * 4 + 2].x += xb.z * w.x; acc[b4 * 4 + 2].y += xb.z * w.y;
                acc[b4 * 4 + 2].z += xb.z * w.z; acc[b4 * 4 + 2].w += xb.z * w.w;
                acc[b4 * 4 + 3].x += xb.w * w.x; acc[b4 * 4 + 3].y += xb.w * w.y;
                acc[b4 * 4 + 3].z += xb.w * w.z; acc[b4 * 4 + 3].w += xb.w * w.w;
            }
        }
        __syncthreads();
    }
    float4* P4 = (float4*)part;
#pragma unroll
    for (int b = 0; b < 16; b++) P4[b * (NCOL / 4) + (j4 >> 2)] = acc[b];
}

__global__ __launch_bounds__(128)
void gemm_qkv(const float* __restrict__ x, const float* __restrict__ wq,
              const float* __restrict__ wk, const float* __restrict__ wv)
{
    const float* W = (blockIdx.z == 0) ? wq : (blockIdx.z == 1 ? wk : wv);
    float* part = g_part + ((size_t)blockIdx.z * KS + blockIdx.y) * BN;
    gemm16_body(x, W, part);
}

__global__ __launch_bounds__(128)
void gemm_out(const float* __restrict__ wo)
{
    float* part = g_cpart + (size_t)blockIdx.y * BN;
    gemm16_body(g_ctx, wo, part);
}

__global__ __launch_bounds__(256)
void reduce_qkv()
{
    int i = blockIdx.x * 256 + threadIdx.x;
    if (i < 3 * BN) {
        int mat = i >> 16;
        int r   = i & (BN - 1);
        const float* p = g_part + (size_t)mat * KS * BN + r;
        float s = 0.f;
#pragma unroll 8
        for (int k = 0; k < KS; k++) s += p[(size_t)k * BN];
        g_qkv[i] = s;
    }
}

__global__ __launch_bounds__(256)
void reduce_out(float* __restrict__ out)
{
    int i = blockIdx.x * 256 + threadIdx.x;
    if (i < BN) {
        const float* p = g_cpart + i;
        float s = 0.f;
#pragma unroll 8
        for (int k = 0; k < KS; k++) s += p[(size_t)k * BN];
        out[i] = s;
    }
}

// ---------------------------------------------------------------------------
// Split attention: block (b, h, t) handles keys [t*512, (t+1)*512).
// pass1: warp-per-k K dot (float4 + shfl), write pre-softmax scores to out.
// local softmax stats (m_t, s_t), scaled exp weights, partial ctx over V.
// k == 4095 (tile NT-1) redirected to fresh xk/xv.
// ---------------------------------------------------------------------------
__global__ __launch_bounds__(256)
void attn_tile(const float* __restrict__ ck, const float* __restrict__ cv,
               const float* __restrict__ mask, float* __restrict__ out)
{
    const int b = blockIdx.x, h = blockIdx.y, t = blockIdx.z;
    const int tid = threadIdx.x, lane = tid & 31, wp = tid >> 5;
    const int k0 = t * TSZ;

    __shared__ __align__(16) float sc[TSZ];
    __shared__ __align__(16) float qs[DH];
    __shared__ float redm[8], reds[8];
    __shared__ __align__(16) float vpart[8][DH];

    if (tid < DH) qs[tid] = g_qkv[(size_t)b * NCOL + h * DH + tid];
    __syncthreads();

    const float4 qf = ((const float4*)qs)[lane];
    const float* kbase = ck + ((size_t)b << 24) + (size_t)h * DH;
    const float* knew  = g_qkv + BN + (size_t)b * NCOL + h * DH;
    const float scale = 0.08838834764831845f;   // 1/sqrt(128)
    float* wout = out + ((size_t)(b * NH + h)) * SEQ;

    // pass 1: scores for this tile (8 warps, 64 rows each)
#pragma unroll 8
    for (int i = 0; i < TSZ / 8; i++) {
        int k = k0 + wp + i * 8;
        const float* row = (k == SEQ - 1) ? knew : (kbase + (size_t)k * NCOL);
        float4 kf = ((const float4*)row)[lane];
        float p = kf.x * qf.x + kf.y * qf.y + kf.z * qf.z + kf.w * qf.w;
        p += __shfl_xor_sync(0xffffffffu, p, 16);
        p += __shfl_xor_sync(0xffffffffu, p, 8);
        p += __shfl_xor_sync(0xffffffffu, p, 4);
        p += __shfl_xor_sync(0xffffffffu, p, 2);
        p += __shfl_xor_sync(0xffffffffu, p, 1);
        if (lane == 0) sc[k - k0] = p * scale + mask[k];
    }
    __syncthreads();

    // coalesced score output write + local max
    float m = -1e30f;
#pragma unroll
    for (int i = tid; i < TSZ; i += 256) {
        float s = sc[i];
        wout[k0 + i] = s;
        m = fmaxf(m, s);
    }
#pragma unroll
    for (int o = 16; o; o >>= 1) m = fmaxf(m, __shfl_xor_sync(0xffffffffu, m, o));
    if (lane == 0) redm[wp] = m;
    __syncthreads();
    float M = redm[0];
#pragma unroll
    for (int i = 1; i < 8; i++) M = fmaxf(M, redm[i]);

    // local expsum
    float sum = 0.f;
#pragma unroll
    for (int i = tid; i < TSZ; i += 256) {
        float e = __expf(sc[i] - M);
        sc[i] = e;
        sum += e;
    }
#pragma unroll
    for (int o = 16; o; o >>= 1) sum += __shfl_xor_sync(0xffffffffu, sum, o);
    if (lane == 0) reds[wp] = sum;
    __syncthreads();

    // pass 2: partial ctx over this tile's V rows (warp-per-row, float4)
    const float4* vrow4 = (const float4*)(cv + ((size_t)b << 24) + (size_t)h * DH);
    const float4* vnew4 = (const float4*)(g_qkv + 2 * BN + (size_t)b * NCOL + h * DH);
    float4 a4 = make_float4(0.f, 0.f, 0.f, 0.f);
#pragma unroll 8
    for (int i = 0; i < TSZ / 8; i++) {
        int k = k0 + wp + i * 8;
        float w = sc[k - k0];
        float4 v = (k == SEQ - 1) ? vnew4[lane]
                                  : vrow4[(size_t)k * (NCOL / 4) + lane];
        a4.x += w * v.x; a4.y += w * v.y; a4.z += w * v.z; a4.w += w * v.w;
    }
    ((float4*)vpart[wp])[lane] = a4;
    __syncthreads();

    const int idx = (b * NH + h) * NT + t;
    if (tid < DH) {
        float s = 0.f;
#pragma unroll
        for (int i = 0; i < 8; i++) s += vpart[i][tid];
        g_actx[(size_t)idx * DH + tid] = s;
    }
    if (tid == 0) {
        float S = 0.f;
#pragma unroll
        for (int i = 0; i < 8; i++) S += reds[i];
        g_am[idx] = M;
        g_as[idx] = S;
    }
}

// combine NT tiles per (b,h): global softmax renormalization
__global__ __launch_bounds__(128)
void attn_combine()
{
    const int bh = blockIdx.x;          // b*NH + h
    const int tid = threadIdx.x;
    const int base = bh * NT;

    float mv[NT], sv[NT];
#pragma unroll
    for (int i = 0; i < NT; i++) { mv[i] = g_am[base + i]; sv[i] = g_as[base + i]; }
    float M = mv[0];
#pragma unroll
    for (int i = 1; i < NT; i++) M = fmaxf(M, mv[i]);
    float S = 0.f, w[NT];
#pragma unroll
    for (int i = 0; i < NT; i++) { w[i] = __expf(mv[i] - M); S += sv[i] * w[i]; }
    const float rinv = 1.f / S;

    float c = 0.f;
#pragma unroll
    for (int i = 0; i < NT; i++)
        c += w[i] * g_actx[(size_t)(base + i) * DH + tid];

    const int b = bh >> 5, h = bh & 31;
    g_ctx[(size_t)b * NCOL + h * DH + tid] = c * rinv;
}

// ---------------------------------------------------------------------------
extern "C" void kernel_launch(void* const* d_in, const int* in_sizes, int n_in,
                              void* d_out, int out_size)
{
    const float* x    = (const float*)d_in[0];
    const float* mask = (const float*)d_in[1];
    const float* wq   = (const float*)d_in[2];
    const float* wk   = (const float*)d_in[3];
    const float* wv   = (const float*)d_in[4];
    const float* wo   = (const float*)d_in[5];
    const float* ck   = (const float*)d_in[6];
    const float* cv   = (const float*)d_in[7];
    float* out = (float*)d_out;

    gemm_qkv<<<dim3(8, KS, 3), 128>>>(x, wq, wk, wv);
    reduce_qkv<<<(3 * BN) / 256, 256>>>();
    attn_tile<<<dim3(BS, NH, NT), 256>>>(ck, cv, mask, out);
    attn_combine<<<BS * NH, 128>>>();
    gemm_out<<<dim3(8, KS, 1), 128>>>(wo);
    reduce_out<<<BN / 256, 256>>>(out + WEIGHT_ELEMS);
}

// round 4
// speedup vs baseline: 1.0920x; 1.0920x over previous
#include <cuda_runtime.h>
#include <cstdint>

// Problem constants (fixed shapes)
#define BS    16
#define DIM   4096
#define NH    32
#define DH    128
#define SEQ   4096
#define NCOL  4096   // NH*DH
#define KS    64     // K-split for the 16xN GEMMs

#define WEIGHT_ELEMS (BS * NH * SEQ)   // 2097152
#define BN (BS * NCOL)                 // 65536

// Scratch (device globals; no allocation allowed)
__device__ float g_qkv[3 * BN];             // q,k,v : [mat][b][h*128+d]
__device__ float g_part[3 * KS * BN];       // qkv GEMM k-split partials
__device__ float g_ctx[BN];                 // attention context [b][h*128+d]
__device__ float g_cpart[KS * BN];          // out-proj k-split partials

// ---------------------------------------------------------------------------
// 16xK @ KxN GEMM body: 128 threads, each thread owns 2 consecutive output
// columns (float2 W loads) for all 16 batch rows, accumulating with packed
// fma.rn.f32x2 (2 batch lanes per instruction). Block covers 256 columns and
// DIM/KS = 64 K-rows. X staged in smem, read via ld.shared.b64 (pre-paired).
// ---------------------------------------------------------------------------
__device__ __forceinline__ void gemm16_body(const float* __restrict__ X,
                                            const float* __restrict__ W,
                                            float* __restrict__ part)
{
    __shared__ __align__(16) float xs[32][16];
    const int j2 = blockIdx.x * 128 + threadIdx.x;       // float2 column index
    const int d0 = blockIdx.y * (DIM / KS);              // 64 rows per split

    // acc[bp*2+c] = packed {batch 2bp, batch 2bp+1} for column c
    unsigned long long acc[16];
#pragma unroll
    for (int i = 0; i < 16; i++) acc[i] = 0ull;

    const float2* W2 = (const float2*)W;
    const uint32_t xs_sh = (uint32_t)__cvta_generic_to_shared(&xs[0][0]);

    for (int dt = 0; dt < DIM / KS; dt += 32) {
        const int base = d0 + dt;
#pragma unroll
        for (int i = threadIdx.x; i < 512; i += 128) {
            int b = i >> 5, dd = i & 31;
            xs[dd][b] = X[b * DIM + base + dd];
        }
        __syncthreads();
#pragma unroll
        for (int dd = 0; dd < 32; dd++) {
            float2 w = W2[(size_t)(base + dd) * (NCOL / 2) + j2];
            unsigned long long wx, wy;
            asm("mov.b64 %0, {%1, %1};" : "=l"(wx) : "f"(w.x));
            asm("mov.b64 %0, {%1, %1};" : "=l"(wy) : "f"(w.y));
            const uint32_t ra = xs_sh + dd * 64;
#pragma unroll
            for (int bp = 0; bp < 8; bp++) {
                unsigned long long x2;
                asm("ld.shared.b64 %0, [%1];" : "=l"(x2) : "r"(ra + bp * 8));
                asm("fma.rn.f32x2 %0, %1, %2, %0;" : "+l"(acc[bp * 2])     : "l"(x2), "l"(wx));
                asm("fma.rn.f32x2 %0, %1, %2, %0;" : "+l"(acc[bp * 2 + 1]) : "l"(x2), "l"(wy));
            }
        }
        __syncthreads();
    }

    // unpack & store: part[b*NCOL + 2*j2 + c]
    float2* P2 = (float2*)part;
#pragma unroll
    for (int bp = 0; bp < 8; bp++) {
        float c0l, c0h, c1l, c1h;
        asm("mov.b64 {%0, %1}, %2;" : "=f"(c0l), "=f"(c0h) : "l"(acc[bp * 2]));
        asm("mov.b64 {%0, %1}, %2;" : "=f"(c1l), "=f"(c1h) : "l"(acc[bp * 2 + 1]));
        P2[(bp * 2 + 0) * (NCOL / 2) + j2] = make_float2(c0l, c1l);
        P2[(bp * 2 + 1) * (NCOL / 2) + j2] = make_float2(c0h, c1h);
    }
}

__global__ __launch_bounds__(128)
void gemm_qkv(const float* __restrict__ x, const float* __restrict__ wq,
              const float* __restrict__ wk, const float* __restrict__ wv)
{
    const float* W = (blockIdx.z == 0) ? wq : (blockIdx.z == 1 ? wk : wv);
    float* part = g_part + ((size_t)blockIdx.z * KS + blockIdx.y) * BN;
    gemm16_body(x, W, part);
}

__global__ __launch_bounds__(128)
void gemm_out(const float* __restrict__ wo)
{
    float* part = g_cpart + (size_t)blockIdx.y * BN;
    gemm16_body(g_ctx, wo, part);
}

__global__ __launch_bounds__(256)
void reduce_qkv()
{
    int i = blockIdx.x * 256 + threadIdx.x;
    if (i < 3 * BN) {
        int mat = i >> 16;
        int r   = i & (BN - 1);
        const float* p = g_part + (size_t)mat * KS * BN + r;
        float s = 0.f;
#pragma unroll 8
        for (int k = 0; k < KS; k++) s += p[(size_t)k * BN];
        g_qkv[i] = s;
    }
}

__global__ __launch_bounds__(256)
void reduce_out(float* __restrict__ out)
{
    int i = blockIdx.x * 256 + threadIdx.x;
    if (i < BN) {
        const float* p = g_cpart + i;
        float s = 0.f;
#pragma unroll 8
        for (int k = 0; k < KS; k++) s += p[(size_t)k * BN];
        out[i] = s;
    }
}

// ---------------------------------------------------------------------------
// Fused attention per (b,h), 512 threads (round-2 form: near HBM roofline).
// pass1: warp-per-k (float4 K loads, shfl reduce) -> scores into smem
// coalesced weight write + softmax -> pass2: 16 k-stripes x 32-lane float4
// V loads. k == 4095 redirected to fresh xk/xv (cache update semantics).
// ---------------------------------------------------------------------------
__global__ __launch_bounds__(512)
void attn_kernel(const float* __restrict__ ck, const float* __restrict__ cv,
                 const float* __restrict__ mask, float* __restrict__ out)
{
    const int b = blockIdx.x, h = blockIdx.y;
    const int tid = threadIdx.x, lane = tid & 31, wp = tid >> 5;

    __shared__ float sc[SEQ];          // scores -> exp weights
    __shared__ __align__(16) float qs[DH];
    __shared__ float redm[16], reds[16];
    __shared__ __align__(16) float cp[16][DH];

    if (tid < DH) qs[tid] = g_qkv[(size_t)b * NCOL + h * DH + tid];
    __syncthreads();

    const float4 qf = ((const float4*)qs)[lane];
    const float* kbase = ck + ((size_t)b << 24) + (size_t)h * DH;   // b*SEQ*NCOL
    const float* knew  = g_qkv + BN + (size_t)b * NCOL + h * DH;    // xk row
    const float scale = 0.08838834764831845f;                        // 1/sqrt(128)
    float* wout = out + ((size_t)(b * NH + h)) * SEQ;

    // pass 1: scores (16 warps, 256 rows each)
#pragma unroll 4
    for (int k = wp; k < SEQ; k += 16) {
        const float* row = (k == SEQ - 1) ? knew : (kbase + (size_t)k * NCOL);
        float4 kf = ((const float4*)row)[lane];
        float p = kf.x * qf.x + kf.y * qf.y + kf.z * qf.z + kf.w * qf.w;
        p += __shfl_xor_sync(0xffffffffu, p, 16);
        p += __shfl_xor_sync(0xffffffffu, p, 8);
        p += __shfl_xor_sync(0xffffffffu, p, 4);
        p += __shfl_xor_sync(0xffffffffu, p, 2);
        p += __shfl_xor_sync(0xffffffffu, p, 1);
        if (lane == 0) sc[k] = p * scale + mask[k];
    }
    __syncthreads();

    // coalesced weight output write + max reduce
    float m = -1e30f;
    for (int i = tid; i < SEQ; i += 512) {
        float s = sc[i];
        wout[i] = s;
        m = fmaxf(m, s);
    }
#pragma unroll
    for (int o = 16; o; o >>= 1) m = fmaxf(m, __shfl_xor_sync(0xffffffffu, m, o));
    if (lane == 0) redm[wp] = m;
    __syncthreads();
    float M = redm[0];
#pragma unroll
    for (int i = 1; i < 16; i++) M = fmaxf(M, redm[i]);

    float sum = 0.f;
    for (int i = tid; i < SEQ; i += 512) {
        float e = __expf(sc[i] - M);
        sc[i] = e;
        sum += e;
    }
#pragma unroll
    for (int o = 16; o; o >>= 1) sum += __shfl_xor_sync(0xffffffffu, sum, o);
    if (lane == 0) reds[wp] = sum;
    __syncthreads();
    float S = 0.f;
#pragma unroll
    for (int i = 0; i < 16; i++) S += reds[i];
    const float rinv = 1.f / S;

    // pass 2: ctx[d] = sum_k attn[k] * V[b,k,h,d]; 16 k-stripes, float4 loads
    const float4* vrow4 = (const float4*)(cv + ((size_t)b << 24) + (size_t)h * DH);
    float4 a4 = make_float4(0.f, 0.f, 0.f, 0.f);
    const int k0 = wp * 256;
    const int k1 = k0 + 256 - (wp == 15 ? 1 : 0);   // stripe 15 stops at 4094
#pragma unroll 8
    for (int k = k0; k < k1; k++) {
        float w = sc[k];
        float4 v = vrow4[(size_t)k * (NCOL / 4) + lane];
        a4.x += w * v.x; a4.y += w * v.y; a4.z += w * v.z; a4.w += w * v.w;
    }
    if (wp == 15) {
        float w = sc[SEQ - 1];
        float4 v = ((const float4*)(g_qkv + 2 * BN + (size_t)b * NCOL + h * DH))[lane];
        a4.x += w * v.x; a4.y += w * v.y; a4.z += w * v.z; a4.w += w * v.w;
    }
    ((float4*)cp[wp])[lane] = a4;
    __syncthreads();

    if (tid < DH) {
        float s = 0.f;
#pragma unroll
        for (int i = 0; i < 16; i++) s += cp[i][tid];
        g_ctx[(size_t)b * NCOL + h * DH + tid] = s * rinv;
    }
}

// ---------------------------------------------------------------------------
extern "C" void kernel_launch(void* const* d_in, const int* in_sizes, int n_in,
                              void* d_out, int out_size)
{
    const float* x    = (const float*)d_in[0];
    const float* mask = (const float*)d_in[1];
    const float* wq   = (const float*)d_in[2];
    const float* wk   = (const float*)d_in[3];
    const float* wv   = (const float*)d_in[4];
    const float* wo   = (const float*)d_in[5];
    const float* ck   = (const float*)d_in[6];
    const float* cv   = (const float*)d_in[7];
    float* out = (float*)d_out;

    gemm_qkv<<<dim3(16, KS, 3), 128>>>(x, wq, wk, wv);
    reduce_qkv<<<(3 * BN) / 256, 256>>>();
    attn_kernel<<<dim3(BS, NH), 512>>>(ck, cv, mask, out);
    gemm_out<<<dim3(16, KS, 1), 128>>>(wo);
    reduce_out<<<BN / 256, 256>>>(out + WEIGHT_ELEMS);
}

// round 5
// speedup vs baseline: 1.0925x; 1.0005x over previous
#include <cuda_runtime.h>
#include <cstdint>

// Problem constants (fixed shapes)
#define BS    16
#define DIM   4096
#define NH    32
#define DH    128
#define SEQ   4096
#define NCOL  4096   // NH*DH
#define KS    64     // K-split for the 16xN GEMMs

#define WEIGHT_ELEMS (BS * NH * SEQ)   // 2097152
#define BN (BS * NCOL)                 // 65536

// Scratch (device globals; no allocation allowed)
__device__ float g_qkv[3 * BN];             // q,k,v : [mat][b][h*128+d]
__device__ float g_part[3 * KS * BN];       // qkv GEMM k-split partials
__device__ float g_ctx[BN];                 // attention context [b][h*128+d]
__device__ float g_cpart[KS * BN];          // out-proj k-split partials

// ---------------------------------------------------------------------------
// 16xK @ KxN GEMM body: 128 threads, each thread owns 2 consecutive output
// columns for all 16 batch rows (fma.rn.f32x2, 2 batch lanes per instr).
// All 64 K-rows of X staged once in smem. W loads batched 8-deep and
// software-pipelined (8 independent LDG.64 in flight per thread).
// ---------------------------------------------------------------------------
__device__ __forceinline__ void gemm16_body(const float* __restrict__ X,
                                            const float* __restrict__ W,
                                            float* __restrict__ part)
{
    __shared__ __align__(16) float xs[64][16];
    const int j2 = blockIdx.x * 128 + threadIdx.x;       // float2 column index
    const int d0 = blockIdx.y * (DIM / KS);              // 64 rows per split

    // stage all 64 K-rows x 16 batch of X (one barrier total)
#pragma unroll
    for (int i = threadIdx.x; i < 1024; i += 128) {
        int b = i >> 6, dd = i & 63;
        xs[dd][b] = X[b * DIM + d0 + dd];
    }

    unsigned long long acc[16];
#pragma unroll
    for (int i = 0; i < 16; i++) acc[i] = 0ull;

    const float2* W2 = (const float2*)W + j2;
    const uint32_t xs_sh = (uint32_t)__cvta_generic_to_shared(&xs[0][0]);

    __syncthreads();

    float2 w[8], wn[8];
    // prologue: load group 0 (rows d0..d0+7), 8 independent LDG.64
#pragma unroll
    for (int r = 0; r < 8; r++)
        w[r] = W2[(size_t)(d0 + r) * (NCOL / 2)];

#pragma unroll
    for (int g = 0; g < 8; g++) {
        // prefetch next group while computing current
        if (g < 7) {
#pragma unroll
            for (int r = 0; r < 8; r++)
                wn[r] = W2[(size_t)(d0 + (g + 1) * 8 + r) * (NCOL / 2)];
        }
#pragma unroll
        for (int r = 0; r < 8; r++) {
            unsigned long long wx, wy;
            asm("mov.b64 %0, {%1, %1};" : "=l"(wx) : "f"(w[r].x));
            asm("mov.b64 %0, {%1, %1};" : "=l"(wy) : "f"(w[r].y));
            const uint32_t ra = xs_sh + (g * 8 + r) * 64;
#pragma unroll
            for (int bp = 0; bp < 8; bp++) {
                unsigned long long x2;
                asm("ld.shared.b64 %0, [%1];" : "=l"(x2) : "r"(ra + bp * 8));
                asm("fma.rn.f32x2 %0, %1, %2, %0;" : "+l"(acc[bp * 2])     : "l"(x2), "l"(wx));
                asm("fma.rn.f32x2 %0, %1, %2, %0;" : "+l"(acc[bp * 2 + 1]) : "l"(x2), "l"(wy));
            }
        }
#pragma unroll
        for (int r = 0; r < 8; r++) w[r] = wn[r];
    }

    // unpack & store: part[b*NCOL + 2*j2 + c]
    float2* P2 = (float2*)part;
#pragma unroll
    for (int bp = 0; bp < 8; bp++) {
        float c0l, c0h, c1l, c1h;
        asm("mov.b64 {%0, %1}, %2;" : "=f"(c0l), "=f"(c0h) : "l"(acc[bp * 2]));
        asm("mov.b64 {%0, %1}, %2;" : "=f"(c1l), "=f"(c1h) : "l"(acc[bp * 2 + 1]));
        P2[(bp * 2 + 0) * (NCOL / 2) + j2] = make_float2(c0l, c1l);
        P2[(bp * 2 + 1) * (NCOL / 2) + j2] = make_float2(c0h, c1h);
    }
}

__global__ __launch_bounds__(128)
void gemm_qkv(const float* __restrict__ x, const float* __restrict__ wq,
              const float* __restrict__ wk, const float* __restrict__ wv)
{
    const float* W = (blockIdx.z == 0) ? wq : (blockIdx.z == 1 ? wk : wv);
    float* part = g_part + ((size_t)blockIdx.z * KS + blockIdx.y) * BN;
    gemm16_body(x, W, part);
}

__global__ __launch_bounds__(128)
void gemm_out(const float* __restrict__ wo)
{
    float* part = g_cpart + (size_t)blockIdx.y * BN;
    gemm16_body(g_ctx, wo, part);
}

__global__ __launch_bounds__(256)
void reduce_qkv()
{
    int i = blockIdx.x * 256 + threadIdx.x;
    if (i < 3 * BN) {
        int mat = i >> 16;
        int r   = i & (BN - 1);
        const float* p = g_part + (size_t)mat * KS * BN + r;
        float s = 0.f;
#pragma unroll 8
        for (int k = 0; k < KS; k++) s += p[(size_t)k * BN];
        g_qkv[i] = s;
    }
}

__global__ __launch_bounds__(256)
void reduce_out(float* __restrict__ out)
{
    int i = blockIdx.x * 256 + threadIdx.x;
    if (i < BN) {
        const float* p = g_cpart + i;
        float s = 0.f;
#pragma unroll 8
        for (int k = 0; k < KS; k++) s += p[(size_t)k * BN];
        out[i] = s;
    }
}

// ---------------------------------------------------------------------------
// Fused attention per (b,h), 512 threads (near HBM roofline — unchanged).
// ---------------------------------------------------------------------------
__global__ __launch_bounds__(512)
void attn_kernel(const float* __restrict__ ck, const float* __restrict__ cv,
                 const float* __restrict__ mask, float* __restrict__ out)
{
    const int b = blockIdx.x, h = blockIdx.y;
    const int tid = threadIdx.x, lane = tid & 31, wp = tid >> 5;

    __shared__ float sc[SEQ];          // scores -> exp weights
    __shared__ __align__(16) float qs[DH];
    __shared__ float redm[16], reds[16];
    __shared__ __align__(16) float cp[16][DH];

    if (tid < DH) qs[tid] = g_qkv[(size_t)b * NCOL + h * DH + tid];
    __syncthreads();

    const float4 qf = ((const float4*)qs)[lane];
    const float* kbase = ck + ((size_t)b << 24) + (size_t)h * DH;   // b*SEQ*NCOL
    const float* knew  = g_qkv + BN + (size_t)b * NCOL + h * DH;    // xk row
    const float scale = 0.08838834764831845f;                        // 1/sqrt(128)
    float* wout = out + ((size_t)(b * NH + h)) * SEQ;

    // pass 1: scores (16 warps, 256 rows each)
#pragma unroll 4
    for (int k = wp; k < SEQ; k += 16) {
        const float* row = (k == SEQ - 1) ? knew : (kbase + (size_t)k * NCOL);
        float4 kf = ((const float4*)row)[lane];
        float p = kf.x * qf.x + kf.y * qf.y + kf.z * qf.z + kf.w * qf.w;
        p += __shfl_xor_sync(0xffffffffu, p, 16);
        p += __shfl_xor_sync(0xffffffffu, p, 8);
        p += __shfl_xor_sync(0xffffffffu, p, 4);
        p += __shfl_xor_sync(0xffffffffu, p, 2);
        p += __shfl_xor_sync(0xffffffffu, p, 1);
        if (lane == 0) sc[k] = p * scale + mask[k];
    }
    __syncthreads();

    // coalesced weight output write + max reduce
    float m = -1e30f;
    for (int i = tid; i < SEQ; i += 512) {
        float s = sc[i];
        wout[i] = s;
        m = fmaxf(m, s);
    }
#pragma unroll
    for (int o = 16; o; o >>= 1) m = fmaxf(m, __shfl_xor_sync(0xffffffffu, m, o));
    if (lane == 0) redm[wp] = m;
    __syncthreads();
    float M = redm[0];
#pragma unroll
    for (int i = 1; i < 16; i++) M = fmaxf(M, redm[i]);

    float sum = 0.f;
    for (int i = tid; i < SEQ; i += 512) {
        float e = __expf(sc[i] - M);
        sc[i] = e;
        sum += e;
    }
#pragma unroll
    for (int o = 16; o; o >>= 1) sum += __shfl_xor_sync(0xffffffffu, sum, o);
    if (lane == 0) reds[wp] = sum;
    __syncthreads();
    float S = 0.f;
#pragma unroll
    for (int i = 0; i < 16; i++) S += reds[i];
    const float rinv = 1.f / S;

    // pass 2: ctx[d] = sum_k attn[k] * V[b,k,h,d]; 16 k-stripes, float4 loads
    const float4* vrow4 = (const float4*)(cv + ((size_t)b << 24) + (size_t)h * DH);
    float4 a4 = make_float4(0.f, 0.f, 0.f, 0.f);
    const int k0 = wp * 256;
    const int k1 = k0 + 256 - (wp == 15 ? 1 : 0);   // stripe 15 stops at 4094
#pragma unroll 8
    for (int k = k0; k < k1; k++) {
        float w = sc[k];
        float4 v = vrow4[(size_t)k * (NCOL / 4) + lane];
        a4.x += w * v.x; a4.y += w * v.y; a4.z += w * v.z; a4.w += w * v.w;
    }
    if (wp == 15) {
        float w = sc[SEQ - 1];
        float4 v = ((const float4*)(g_qkv + 2 * BN + (size_t)b * NCOL + h * DH))[lane];
        a4.x += w * v.x; a4.y += w * v.y; a4.z += w * v.z; a4.w += w * v.w;
    }
    ((float4*)cp[wp])[lane] = a4;
    __syncthreads();

    if (tid < DH) {
        float s = 0.f;
#pragma unroll
        for (int i = 0; i < 16; i++) s += cp[i][tid];
        g_ctx[(size_t)b * NCOL + h * DH + tid] = s * rinv;
    }
}

// ---------------------------------------------------------------------------
extern "C" void kernel_launch(void* const* d_in, const int* in_sizes, int n_in,
                              void* d_out, int out_size)
{
    const float* x    = (const float*)d_in[0];
    const float* mask = (const float*)d_in[1];
    const float* wq   = (const float*)d_in[2];
    const float* wk   = (const float*)d_in[3];
    const float* wv   = (const float*)d_in[4];
    const float* wo   = (const float*)d_in[5];
    const float* ck   = (const float*)d_in[6];
    const float* cv   = (const float*)d_in[7];
    float* out = (float*)d_out;

    gemm_qkv<<<dim3(16, KS, 3), 128>>>(x, wq, wk, wv);
    reduce_qkv<<<(3 * BN) / 256, 256>>>();
    attn_kernel<<<dim3(BS, NH), 512>>>(ck, cv, mask, out);
    gemm_out<<<dim3(16, KS, 1), 128>>>(wo);
    reduce_out<<<BN / 256, 256>>>(out + WEIGHT_ELEMS);
}